// round 12
// baseline (speedup 1.0000x reference)
#include <cuda_runtime.h>
#include <cuda_bf16.h>

#define L_ 50
#define T_ 100
#define D_ 64
#define I_MAX 100000
#define B_MAX 8192
#define WCP 116

typedef unsigned long long ull;
typedef unsigned int u32;

__device__ __nv_bfloat16 g_P[I_MAX * D_];   // item_table @ fg_item_W.T  (bf16)
__device__ float g_ufg[B_MAX * D_];
__device__ float g_t2[B_MAX * L_];

__device__ __forceinline__ ull ffma2(ull a, ull b, ull c) {
    ull d;
    asm("fma.rn.f32x2 %0, %1, %2, %3;" : "=l"(d) : "l"(a), "l"(b), "l"(c));
    return d;
}
__device__ __forceinline__ ull dup2(float x) {
    ull r;
    asm("mov.b64 %0, {%1, %1};" : "=l"(r) : "f"(x));
    return r;
}
__device__ __forceinline__ u32 tf32cvt(float f) {
    u32 r;
    asm("cvt.rna.tf32.f32 %0, %1;" : "=r"(r) : "f"(f));
    return r;
}
__device__ __forceinline__ void mma_tf32(float c[4], u32 a0, u32 a1, u32 a2, u32 a3,
                                         u32 b0, u32 b1) {
    asm("mma.sync.aligned.m16n8k8.row.col.f32.tf32.tf32.f32 "
        "{%0,%1,%2,%3}, {%4,%5,%6,%7}, {%8,%9}, {%0,%1,%2,%3};"
        : "+f"(c[0]), "+f"(c[1]), "+f"(c[2]), "+f"(c[3])
        : "r"(a0), "r"(a1), "r"(a2), "r"(a3), "r"(b0), "r"(b1));
}
__device__ __forceinline__ float sigf(float x) {
    return __fdividef(1.0f, 1.0f + __expf(-x));
}

// ---------------- Fused precompute ----------------
// P branch (tensor cores): 64 rows/CTA, 4 warps x 16 rows, tf32 m16n8k8.
// XOR-swizzled smem: word(r,k) = r*64 + (k ^ ((r&7)<<2)). Fragment loads conflict-free.
struct SmemP { u32 Esw[64 * 64]; u32 Wsw[64 * 64]; };                       // 32KB
struct SmemU { float Wc[64 * WCP]; ull UEd8[16 * 64]; float bs[64]; int uids[16]; };
union SmemPre { SmemP p; SmemU u; };

__global__ __launch_bounds__(128) void k_pre(
    const float* __restrict__ item_table,
    const float* __restrict__ fg_item_W,
    const int*   __restrict__ user_ids,
    const float* __restrict__ user_table,
    const float* __restrict__ fg_user_W,
    const float* __restrict__ fg_item_b,
    const float* __restrict__ fg_user_b,
    const float* __restrict__ inst_gate_user,
    int R, int B, int nP)
{
    __shared__ SmemPre s;
    const int tid = threadIdx.x, warp = tid >> 5, lane = tid & 31;

    if ((int)blockIdx.x < nP) {
        const int r0 = blockIdx.x * 64;
        // W -> tf32 swizzled smem (B operand, col-major view: B[k][n] = W[n][k])
        #pragma unroll
        for (int e = tid; e < 4096; e += 128) {
            int d = e >> 6, k = e & 63;
            s.p.Wsw[d * 64 + (k ^ ((d & 7) << 2))] = tf32cvt(fg_item_W[e]);
        }
        // E rows -> tf32 swizzled smem (A operand)
        const float4* it4 = (const float4*)item_table;
        #pragma unroll
        for (int i = tid; i < 1024; i += 128) {
            int rl = i >> 4, c4 = i & 15;
            int r = r0 + rl; if (r >= R) r = R - 1;
            float4 v = it4[r * 16 + c4];
            uint4 u;
            u.x = tf32cvt(v.x); u.y = tf32cvt(v.y);
            u.z = tf32cvt(v.z); u.w = tf32cvt(v.w);
            *(uint4*)&s.p.Esw[rl * 64 + ((c4 << 2) ^ ((rl & 7) << 2))] = u;
        }
        __syncthreads();

        const int g = lane >> 2, t = lane & 3, sw = g << 2;
        const int rw = warp << 4;                    // local row base (16 rows/warp)
        float c[8][4];
        #pragma unroll
        for (int nt = 0; nt < 8; nt++)
            #pragma unroll
            for (int i = 0; i < 4; i++) c[nt][i] = 0.f;

        #pragma unroll
        for (int kt = 0; kt < 8; kt++) {
            const int k0 = kt << 3;
            u32 a0 = s.p.Esw[(rw + g)     * 64 + ((k0 + t)     ^ sw)];
            u32 a1 = s.p.Esw[(rw + g + 8) * 64 + ((k0 + t)     ^ sw)];
            u32 a2 = s.p.Esw[(rw + g)     * 64 + ((k0 + t + 4) ^ sw)];
            u32 a3 = s.p.Esw[(rw + g + 8) * 64 + ((k0 + t + 4) ^ sw)];
            #pragma unroll
            for (int nt = 0; nt < 8; nt++) {
                const int dn = (nt << 3) + g;
                u32 b0 = s.p.Wsw[dn * 64 + ((k0 + t)     ^ sw)];
                u32 b1 = s.p.Wsw[dn * 64 + ((k0 + t + 4) ^ sw)];
                mma_tf32(c[nt], a0, a1, a2, a3, b0, b1);
            }
        }
        // C fragment: c0,c1 = row g, cols 2t,2t+1; c2,c3 = row g+8
        const int gr0 = r0 + rw + g, gr1 = gr0 + 8;
        #pragma unroll
        for (int nt = 0; nt < 8; nt++) {
            const int col = (nt << 3) + (t << 1);
            if (gr0 < R)
                *(__nv_bfloat162*)(g_P + gr0 * 64 + col) =
                    __floats2bfloat162_rn(c[nt][0], c[nt][1]);
            if (gr1 < R)
                *(__nv_bfloat162*)(g_P + gr1 * 64 + col) =
                    __floats2bfloat162_rn(c[nt][2], c[nt][3]);
        }
    } else {
        // ---------- User branch: ufg + t2 for 16 users (FFMA2) ----------
        const int u0c = (blockIdx.x - nP) * 16;
        #pragma unroll
        for (int e = tid; e < 4096; e += 128) {
            int d = e >> 6, k = e & 63;
            s.u.Wc[k * WCP + d] = fg_user_W[e];
        }
        for (int e = tid; e < 64 * L_; e += 128) {
            int k = e / L_, l = e - k * L_;
            s.u.Wc[k * WCP + 64 + l] = inst_gate_user[e];
        }
        if (tid < 64) s.u.bs[tid] = fg_item_b[tid] + fg_user_b[tid];
        if (tid < 16) {
            int u = u0c + tid;
            s.u.uids[tid] = user_ids[u < B ? u : (B - 1)];
        }
        __syncthreads();
        {
            const float4* ut4 = (const float4*)user_table;
            #pragma unroll
            for (int i = tid; i < 256; i += 128) {
                int uu = i >> 4, c4 = i & 15;
                float4 v = ut4[s.u.uids[uu] * 16 + c4];
                int base = (uu << 6) + (c4 << 2);
                s.u.UEd8[base]     = dup2(v.x);
                s.u.UEd8[base + 1] = dup2(v.y);
                s.u.UEd8[base + 2] = dup2(v.z);
                s.u.UEd8[base + 3] = dup2(v.w);
            }
        }
        __syncthreads();

        const int ub = warp << 2;                     // 4 users per warp
        {   // ufg
            ull acc[4];
            ull binit = *(const ull*)&s.u.bs[lane << 1];
            #pragma unroll
            for (int j = 0; j < 4; j++) acc[j] = binit;
            #pragma unroll 8
            for (int k = 0; k < 64; k++) {
                ull w = *(const ull*)&s.u.Wc[k * WCP + (lane << 1)];
                #pragma unroll
                for (int j = 0; j < 4; j++)
                    acc[j] = ffma2(s.u.UEd8[((ub + j) << 6) + k], w, acc[j]);
            }
            #pragma unroll
            for (int j = 0; j < 4; j++) {
                int u = u0c + ub + j;
                if (u < B) ((ull*)g_ufg)[u * 32 + lane] = acc[j];
            }
        }
        if (lane < 25) {   // t2
            ull acc[4];
            #pragma unroll
            for (int j = 0; j < 4; j++) acc[j] = 0ull;
            #pragma unroll 8
            for (int k = 0; k < 64; k++) {
                ull w = *(const ull*)&s.u.Wc[k * WCP + 64 + (lane << 1)];
                #pragma unroll
                for (int j = 0; j < 4; j++)
                    acc[j] = ffma2(s.u.UEd8[((ub + j) << 6) + k], w, acc[j]);
            }
            #pragma unroll
            for (int j = 0; j < 4; j++) {
                int u = u0c + ub + j;
                if (u < B) *(ull*)&g_t2[u * L_ + (lane << 1)] = acc[j];
            }
        }
    }
}

// ---------------- Main: quarter-warp (8 lanes x 8 dims) per row ----------------
__global__ __launch_bounds__(128) void k_main(
    const int* __restrict__ user_ids,
    const int* __restrict__ item_seq_ids,
    const int* __restrict__ target_item_ids,
    const float* __restrict__ user_table,
    const float* __restrict__ item_table,
    const float* __restrict__ W2_table,
    const float* __restrict__ b2_table,
    const float* __restrict__ inst_gate_item,
    float* __restrict__ out)
{
    __shared__ int   sid[64];
    __shared__ float t2s[64];
    __shared__ float uf[64];
    __shared__ float RU[16 * 64], RS[16 * 64], IS[16];
    __shared__ float v[64];
    __shared__ float s_is;
    __shared__ float outS[104];

    const int b = blockIdx.x;
    const int tid = threadIdx.x;
    const int qw = tid >> 3;             // quarter-warp 0..15
    const int ql = tid & 7;
    const int d8 = ql << 3;              // dims d8..d8+7

    if (tid < 64) {
        int l = tid < L_ ? tid : (L_ - 1);
        sid[tid] = item_seq_ids[b * L_ + l];
        t2s[tid] = g_t2[b * L_ + l];
    } else {
        uf[tid - 64] = g_ufg[b * 64 + (tid - 64)];
    }
    __syncthreads();

    const float4 gi0 = *(const float4*)&inst_gate_item[d8];
    const float4 gi1 = *(const float4*)&inst_gate_item[d8 + 4];
    const float4 uf0 = *(const float4*)&uf[d8];
    const float4 uf1 = *(const float4*)&uf[d8 + 4];

    // ---- l-phase: 4 rounds, row = qw + 16*j, gathers hoisted ----
    int ids_[4]; float t2v[4];
    #pragma unroll
    for (int j = 0; j < 4; j++) { int l = qw + (j << 4); ids_[j] = sid[l]; t2v[j] = t2s[l]; }
    uint4 pr[4]; float4 e0[4], e1[4];
    #pragma unroll
    for (int j = 0; j < 4; j++) pr[j] = *(const uint4*)(g_P + ids_[j] * 64 + d8); // bf16 x8
    #pragma unroll
    for (int j = 0; j < 4; j++) {
        e0[j] = *(const float4*)&item_table[ids_[j] * 64 + d8];
        e1[j] = *(const float4*)&item_table[ids_[j] * 64 + d8 + 4];
    }

    float4 un0 = {0,0,0,0}, un1 = {0,0,0,0}, si0 = {0,0,0,0}, si1 = {0,0,0,0};
    float isum = 0.f;
    #pragma unroll
    for (int j = 0; j < 4; j++) {
        int l = qw + (j << 4);
        float valid = (l < L_) ? 1.f : 0.f;
        const __nv_bfloat162* pb = (const __nv_bfloat162*)&pr[j];
        float2 pa = __bfloat1622float2(pb[0]);
        float2 pbx = __bfloat1622float2(pb[1]);
        float2 pc = __bfloat1622float2(pb[2]);
        float2 pd = __bfloat1622float2(pb[3]);
        float g0 = sigf(pa.x  + uf0.x) * e0[j].x;
        float g1 = sigf(pa.y  + uf0.y) * e0[j].y;
        float g2 = sigf(pbx.x + uf0.z) * e0[j].z;
        float g3 = sigf(pbx.y + uf0.w) * e0[j].w;
        float g4 = sigf(pc.x  + uf1.x) * e1[j].x;
        float g5 = sigf(pc.y  + uf1.y) * e1[j].y;
        float g6 = sigf(pd.x  + uf1.z) * e1[j].z;
        float g7 = sigf(pd.y  + uf1.w) * e1[j].w;
        float t1 = g0*gi0.x + g1*gi0.y + g2*gi0.z + g3*gi0.w
                 + g4*gi1.x + g5*gi1.y + g6*gi1.z + g7*gi1.w;
        t1 += __shfl_xor_sync(0xffffffffu, t1, 4);
        t1 += __shfl_xor_sync(0xffffffffu, t1, 2);
        t1 += __shfl_xor_sync(0xffffffffu, t1, 1);
        float inst = sigf(t1 + t2v[j]) * valid;
        un0.x = fmaf(g0, inst, un0.x); un0.y = fmaf(g1, inst, un0.y);
        un0.z = fmaf(g2, inst, un0.z); un0.w = fmaf(g3, inst, un0.w);
        un1.x = fmaf(g4, inst, un1.x); un1.y = fmaf(g5, inst, un1.y);
        un1.z = fmaf(g6, inst, un1.z); un1.w = fmaf(g7, inst, un1.w);
        si0.x = fmaf(e0[j].x, valid, si0.x); si0.y = fmaf(e0[j].y, valid, si0.y);
        si0.z = fmaf(e0[j].z, valid, si0.z); si0.w = fmaf(e0[j].w, valid, si0.w);
        si1.x = fmaf(e1[j].x, valid, si1.x); si1.y = fmaf(e1[j].y, valid, si1.y);
        si1.z = fmaf(e1[j].z, valid, si1.z); si1.w = fmaf(e1[j].w, valid, si1.w);
        isum += inst;
    }
    *(float4*)&RU[qw * 64 + d8]     = un0;
    *(float4*)&RU[qw * 64 + d8 + 4] = un1;
    *(float4*)&RS[qw * 64 + d8]     = si0;
    *(float4*)&RS[qw * 64 + d8 + 4] = si1;
    if (ql == 0) IS[qw] = isum;
    __syncthreads();

    float av = 0.f, sv = 0.f;
    if (tid < 64) {
        #pragma unroll
        for (int q = 0; q < 16; q++) { av += RU[q * 64 + tid]; sv += RS[q * 64 + tid]; }
    } else if (tid == 64) {
        float q = 0.f;
        #pragma unroll
        for (int i = 0; i < 16; i++) q += IS[i];
        s_is = q;
    }
    __syncthreads();
    if (tid < 64) {
        int uid = user_ids[b];
        v[tid] = user_table[uid * 64 + tid] + __fdividef(av, s_is) + sv;
    }
    __syncthreads();

    // ---- t-phase: 7 rounds (t = qw + 16*j), chunks {4,3} ----
    const float4 v0 = *(const float4*)&v[d8];
    const float4 v1 = *(const float4*)&v[d8 + 4];
    const int* tids = target_item_ids + b * T_;

    #pragma unroll
    for (int c = 0; c < 2; c++) {
        const int j0 = c ? 4 : 0, nj = c ? 3 : 4;
        int wid_[4]; float b2v[4]; float4 w0[4], w1[4];
        #pragma unroll
        for (int j = 0; j < 4; j++) {
            if (j < nj) {
                int t = qw + ((j0 + j) << 4);
                if (t >= T_) t = T_ - 1;
                wid_[j] = tids[t];
            }
        }
        #pragma unroll
        for (int j = 0; j < 4; j++) {
            if (j < nj) {
                w0[j] = *(const float4*)&W2_table[wid_[j] * 64 + d8];
                w1[j] = *(const float4*)&W2_table[wid_[j] * 64 + d8 + 4];
            }
        }
        #pragma unroll
        for (int j = 0; j < 4; j++)
            if (j < nj) b2v[j] = __ldg(&b2_table[wid_[j]]);
        #pragma unroll
        for (int j = 0; j < 4; j++) {
            if (j < nj) {
                float pp = w0[j].x*v0.x + w0[j].y*v0.y + w0[j].z*v0.z + w0[j].w*v0.w
                         + w1[j].x*v1.x + w1[j].y*v1.y + w1[j].z*v1.z + w1[j].w*v1.w;
                pp += __shfl_xor_sync(0xffffffffu, pp, 4);
                pp += __shfl_xor_sync(0xffffffffu, pp, 2);
                pp += __shfl_xor_sync(0xffffffffu, pp, 1);
                int t = qw + ((j0 + j) << 4);
                if (ql == 0 && t < T_) outS[t] = pp + b2v[j];
            }
        }
    }
    __syncthreads();
    if (tid < T_) out[b * T_ + tid] = outS[tid];
}

extern "C" void kernel_launch(void* const* d_in, const int* in_sizes, int n_in,
                              void* d_out, int out_size) {
    const int B = in_sizes[0] > B_MAX ? B_MAX : in_sizes[0];
    int R = in_sizes[4] / D_;
    if (R > I_MAX) R = I_MAX;
    const int nP = (R + 63) / 64;
    const int nU = (B + 15) / 16;

    k_pre<<<nP + nU, 128>>>(
        (const float*)d_in[4], (const float*)d_in[7],
        (const int*)d_in[0], (const float*)d_in[3], (const float*)d_in[9],
        (const float*)d_in[8], (const float*)d_in[10], (const float*)d_in[12],
        R, B, nP);

    k_main<<<B, 128>>>(
        (const int*)d_in[0], (const int*)d_in[1], (const int*)d_in[2],
        (const float*)d_in[3], (const float*)d_in[4], (const float*)d_in[5],
        (const float*)d_in[6], (const float*)d_in[11], (float*)d_out);
}

// round 13
// speedup vs baseline: 1.7259x; 1.7259x over previous
#include <cuda_runtime.h>
#include <cuda_bf16.h>

#define L_ 50
#define T_ 100
#define D_ 64
#define I_MAX 100000
#define B_MAX 8192
#define WCP 116

typedef unsigned long long ull;
typedef unsigned int u32;

__device__ __nv_bfloat16 g_P[I_MAX * D_];   // item_table @ fg_item_W.T  (bf16)
__device__ float g_ufg[B_MAX * D_];
__device__ float g_t2[B_MAX * L_];

__device__ __forceinline__ ull ffma2(ull a, ull b, ull c) {
    ull d;
    asm("fma.rn.f32x2 %0, %1, %2, %3;" : "=l"(d) : "l"(a), "l"(b), "l"(c));
    return d;
}
__device__ __forceinline__ ull dup2(float x) {
    ull r;
    asm("mov.b64 %0, {%1, %1};" : "=l"(r) : "f"(x));
    return r;
}
__device__ __forceinline__ u32 tf32cvt(float f) {
    u32 r;
    asm("cvt.rna.tf32.f32 %0, %1;" : "=r"(r) : "f"(f));
    return r;
}
__device__ __forceinline__ void mma_tf32(float c[4], u32 a0, u32 a1, u32 a2, u32 a3,
                                         u32 b0, u32 b1) {
    asm("mma.sync.aligned.m16n8k8.row.col.f32.tf32.tf32.f32 "
        "{%0,%1,%2,%3}, {%4,%5,%6,%7}, {%8,%9}, {%0,%1,%2,%3};"
        : "+f"(c[0]), "+f"(c[1]), "+f"(c[2]), "+f"(c[3])
        : "r"(a0), "r"(a1), "r"(a2), "r"(a3), "r"(b0), "r"(b1));
}
__device__ __forceinline__ float sigf(float x) {
    return __fdividef(1.0f, 1.0f + __expf(-x));
}

// ---------------- Fused precompute ----------------
// P branch (tensor cores): 64 rows/CTA, 4 warps x 16 rows, tf32 m16n8k8.
// XOR-swizzled smem: word(r,k) = r*64 + (k ^ ((r&7)<<2)). Fragment loads conflict-free.
// Epilogue: C frags -> smem staging (bf16, stride 66) -> coalesced 128B-per-row STG.
struct SmemP { u32 Esw[64 * 64]; u32 Wsw[64 * 64]; };                       // 32KB
struct SmemU { float Wc[64 * WCP]; ull UEd8[16 * 64]; float bs[64]; int uids[16]; };
union SmemPre { SmemP p; SmemU u; };

__global__ __launch_bounds__(128) void k_pre(
    const float* __restrict__ item_table,
    const float* __restrict__ fg_item_W,
    const int*   __restrict__ user_ids,
    const float* __restrict__ user_table,
    const float* __restrict__ fg_user_W,
    const float* __restrict__ fg_item_b,
    const float* __restrict__ fg_user_b,
    const float* __restrict__ inst_gate_user,
    int R, int B, int nP)
{
    __shared__ SmemPre s;
    const int tid = threadIdx.x, warp = tid >> 5, lane = tid & 31;

    if ((int)blockIdx.x < nP) {
        const int r0 = blockIdx.x * 64;
        // W -> tf32 swizzled smem (B operand, col-major view: B[k][n] = W[n][k])
        #pragma unroll
        for (int e = tid; e < 4096; e += 128) {
            int d = e >> 6, k = e & 63;
            s.p.Wsw[d * 64 + (k ^ ((d & 7) << 2))] = tf32cvt(fg_item_W[e]);
        }
        // E rows -> tf32 swizzled smem (A operand)
        const float4* it4 = (const float4*)item_table;
        #pragma unroll
        for (int i = tid; i < 1024; i += 128) {
            int rl = i >> 4, c4 = i & 15;
            int r = r0 + rl; if (r >= R) r = R - 1;
            float4 v = it4[r * 16 + c4];
            uint4 u;
            u.x = tf32cvt(v.x); u.y = tf32cvt(v.y);
            u.z = tf32cvt(v.z); u.w = tf32cvt(v.w);
            *(uint4*)&s.p.Esw[rl * 64 + ((c4 << 2) ^ ((rl & 7) << 2))] = u;
        }
        __syncthreads();

        const int g = lane >> 2, t = lane & 3, sw = g << 2;
        const int rw = warp << 4;                    // local row base (16 rows/warp)
        float c[8][4];
        #pragma unroll
        for (int nt = 0; nt < 8; nt++)
            #pragma unroll
            for (int i = 0; i < 4; i++) c[nt][i] = 0.f;

        #pragma unroll
        for (int kt = 0; kt < 8; kt++) {
            const int k0 = kt << 3;
            u32 a0 = s.p.Esw[(rw + g)     * 64 + ((k0 + t)     ^ sw)];
            u32 a1 = s.p.Esw[(rw + g + 8) * 64 + ((k0 + t)     ^ sw)];
            u32 a2 = s.p.Esw[(rw + g)     * 64 + ((k0 + t + 4) ^ sw)];
            u32 a3 = s.p.Esw[(rw + g + 8) * 64 + ((k0 + t + 4) ^ sw)];
            #pragma unroll
            for (int nt = 0; nt < 8; nt++) {
                const int dn = (nt << 3) + g;
                u32 b0 = s.p.Wsw[dn * 64 + ((k0 + t)     ^ sw)];
                u32 b1 = s.p.Wsw[dn * 64 + ((k0 + t + 4) ^ sw)];
                mma_tf32(c[nt], a0, a1, a2, a3, b0, b1);
            }
        }
        __syncthreads();                             // done reading Esw -> reuse as staging

        // Stage C frags to smem (scattered STS is cheap; no sector penalty)
        __nv_bfloat16* Pst = (__nv_bfloat16*)s.p.Esw;   // [64][66]
        const int rl0 = rw + g;
        #pragma unroll
        for (int nt = 0; nt < 8; nt++) {
            const int col = (nt << 3) + (t << 1);
            *(__nv_bfloat162*)&Pst[rl0 * 66 + col] =
                __floats2bfloat162_rn(c[nt][0], c[nt][1]);
            *(__nv_bfloat162*)&Pst[(rl0 + 8) * 66 + col] =
                __floats2bfloat162_rn(c[nt][2], c[nt][3]);
        }
        __syncthreads();

        // Coalesced store: each warp-instruction writes one full 128B g_P row
        u32* Pw = (u32*)g_P;
        #pragma unroll
        for (int i = 0; i < 16; i++) {
            int idx = tid + (i << 7);                // 0..2047 = 64 rows x 32 words
            int row = idx >> 5, w = idx & 31;
            int r = r0 + row;
            if (r < R)
                Pw[r * 32 + w] = *(const u32*)&Pst[row * 66 + (w << 1)];
        }
    } else {
        // ---------- User branch: ufg + t2 for 16 users (FFMA2) ----------
        const int u0c = (blockIdx.x - nP) * 16;
        #pragma unroll
        for (int e = tid; e < 4096; e += 128) {
            int d = e >> 6, k = e & 63;
            s.u.Wc[k * WCP + d] = fg_user_W[e];
        }
        for (int e = tid; e < 64 * L_; e += 128) {
            int k = e / L_, l = e - k * L_;
            s.u.Wc[k * WCP + 64 + l] = inst_gate_user[e];
        }
        if (tid < 64) s.u.bs[tid] = fg_item_b[tid] + fg_user_b[tid];
        if (tid < 16) {
            int u = u0c + tid;
            s.u.uids[tid] = user_ids[u < B ? u : (B - 1)];
        }
        __syncthreads();
        {
            const float4* ut4 = (const float4*)user_table;
            #pragma unroll
            for (int i = tid; i < 256; i += 128) {
                int uu = i >> 4, c4 = i & 15;
                float4 v = ut4[s.u.uids[uu] * 16 + c4];
                int base = (uu << 6) + (c4 << 2);
                s.u.UEd8[base]     = dup2(v.x);
                s.u.UEd8[base + 1] = dup2(v.y);
                s.u.UEd8[base + 2] = dup2(v.z);
                s.u.UEd8[base + 3] = dup2(v.w);
            }
        }
        __syncthreads();

        const int ub = warp << 2;                     // 4 users per warp
        {   // ufg
            ull acc[4];
            ull binit = *(const ull*)&s.u.bs[lane << 1];
            #pragma unroll
            for (int j = 0; j < 4; j++) acc[j] = binit;
            #pragma unroll 8
            for (int k = 0; k < 64; k++) {
                ull w = *(const ull*)&s.u.Wc[k * WCP + (lane << 1)];
                #pragma unroll
                for (int j = 0; j < 4; j++)
                    acc[j] = ffma2(s.u.UEd8[((ub + j) << 6) + k], w, acc[j]);
            }
            #pragma unroll
            for (int j = 0; j < 4; j++) {
                int u = u0c + ub + j;
                if (u < B) ((ull*)g_ufg)[u * 32 + lane] = acc[j];
            }
        }
        if (lane < 25) {   // t2
            ull acc[4];
            #pragma unroll
            for (int j = 0; j < 4; j++) acc[j] = 0ull;
            #pragma unroll 8
            for (int k = 0; k < 64; k++) {
                ull w = *(const ull*)&s.u.Wc[k * WCP + 64 + (lane << 1)];
                #pragma unroll
                for (int j = 0; j < 4; j++)
                    acc[j] = ffma2(s.u.UEd8[((ub + j) << 6) + k], w, acc[j]);
            }
            #pragma unroll
            for (int j = 0; j < 4; j++) {
                int u = u0c + ub + j;
                if (u < B) *(ull*)&g_t2[u * L_ + (lane << 1)] = acc[j];
            }
        }
    }
}

// ---------------- Main: quarter-warp (8 lanes x 8 dims) per row ----------------
__global__ __launch_bounds__(128) void k_main(
    const int* __restrict__ user_ids,
    const int* __restrict__ item_seq_ids,
    const int* __restrict__ target_item_ids,
    const float* __restrict__ user_table,
    const float* __restrict__ item_table,
    const float* __restrict__ W2_table,
    const float* __restrict__ b2_table,
    const float* __restrict__ inst_gate_item,
    float* __restrict__ out)
{
    __shared__ int   sid[64];
    __shared__ float t2s[64];
    __shared__ float uf[64];
    __shared__ float RU[16 * 64], RS[16 * 64], IS[16];
    __shared__ float v[64];
    __shared__ float s_is;
    __shared__ float outS[104];

    const int b = blockIdx.x;
    const int tid = threadIdx.x;
    const int qw = tid >> 3;             // quarter-warp 0..15
    const int ql = tid & 7;
    const int d8 = ql << 3;              // dims d8..d8+7

    if (tid < 64) {
        int l = tid < L_ ? tid : (L_ - 1);
        sid[tid] = item_seq_ids[b * L_ + l];
        t2s[tid] = g_t2[b * L_ + l];
    } else {
        uf[tid - 64] = g_ufg[b * 64 + (tid - 64)];
    }
    __syncthreads();

    const float4 gi0 = *(const float4*)&inst_gate_item[d8];
    const float4 gi1 = *(const float4*)&inst_gate_item[d8 + 4];
    const float4 uf0 = *(const float4*)&uf[d8];
    const float4 uf1 = *(const float4*)&uf[d8 + 4];

    // ---- l-phase: 4 rounds, row = qw + 16*j, gathers hoisted ----
    int ids_[4]; float t2v[4];
    #pragma unroll
    for (int j = 0; j < 4; j++) { int l = qw + (j << 4); ids_[j] = sid[l]; t2v[j] = t2s[l]; }
    uint4 pr[4]; float4 e0[4], e1[4];
    #pragma unroll
    for (int j = 0; j < 4; j++) pr[j] = *(const uint4*)(g_P + ids_[j] * 64 + d8); // bf16 x8
    #pragma unroll
    for (int j = 0; j < 4; j++) {
        e0[j] = *(const float4*)&item_table[ids_[j] * 64 + d8];
        e1[j] = *(const float4*)&item_table[ids_[j] * 64 + d8 + 4];
    }

    float4 un0 = {0,0,0,0}, un1 = {0,0,0,0}, si0 = {0,0,0,0}, si1 = {0,0,0,0};
    float isum = 0.f;
    #pragma unroll
    for (int j = 0; j < 4; j++) {
        int l = qw + (j << 4);
        float valid = (l < L_) ? 1.f : 0.f;
        const __nv_bfloat162* pb = (const __nv_bfloat162*)&pr[j];
        float2 pa = __bfloat1622float2(pb[0]);
        float2 pbx = __bfloat1622float2(pb[1]);
        float2 pc = __bfloat1622float2(pb[2]);
        float2 pd = __bfloat1622float2(pb[3]);
        float g0 = sigf(pa.x  + uf0.x) * e0[j].x;
        float g1 = sigf(pa.y  + uf0.y) * e0[j].y;
        float g2 = sigf(pbx.x + uf0.z) * e0[j].z;
        float g3 = sigf(pbx.y + uf0.w) * e0[j].w;
        float g4 = sigf(pc.x  + uf1.x) * e1[j].x;
        float g5 = sigf(pc.y  + uf1.y) * e1[j].y;
        float g6 = sigf(pd.x  + uf1.z) * e1[j].z;
        float g7 = sigf(pd.y  + uf1.w) * e1[j].w;
        float t1 = g0*gi0.x + g1*gi0.y + g2*gi0.z + g3*gi0.w
                 + g4*gi1.x + g5*gi1.y + g6*gi1.z + g7*gi1.w;
        t1 += __shfl_xor_sync(0xffffffffu, t1, 4);
        t1 += __shfl_xor_sync(0xffffffffu, t1, 2);
        t1 += __shfl_xor_sync(0xffffffffu, t1, 1);
        float inst = sigf(t1 + t2v[j]) * valid;
        un0.x = fmaf(g0, inst, un0.x); un0.y = fmaf(g1, inst, un0.y);
        un0.z = fmaf(g2, inst, un0.z); un0.w = fmaf(g3, inst, un0.w);
        un1.x = fmaf(g4, inst, un1.x); un1.y = fmaf(g5, inst, un1.y);
        un1.z = fmaf(g6, inst, un1.z); un1.w = fmaf(g7, inst, un1.w);
        si0.x = fmaf(e0[j].x, valid, si0.x); si0.y = fmaf(e0[j].y, valid, si0.y);
        si0.z = fmaf(e0[j].z, valid, si0.z); si0.w = fmaf(e0[j].w, valid, si0.w);
        si1.x = fmaf(e1[j].x, valid, si1.x); si1.y = fmaf(e1[j].y, valid, si1.y);
        si1.z = fmaf(e1[j].z, valid, si1.z); si1.w = fmaf(e1[j].w, valid, si1.w);
        isum += inst;
    }
    *(float4*)&RU[qw * 64 + d8]     = un0;
    *(float4*)&RU[qw * 64 + d8 + 4] = un1;
    *(float4*)&RS[qw * 64 + d8]     = si0;
    *(float4*)&RS[qw * 64 + d8 + 4] = si1;
    if (ql == 0) IS[qw] = isum;
    __syncthreads();

    float av = 0.f, sv = 0.f;
    if (tid < 64) {
        #pragma unroll
        for (int q = 0; q < 16; q++) { av += RU[q * 64 + tid]; sv += RS[q * 64 + tid]; }
    } else if (tid == 64) {
        float q = 0.f;
        #pragma unroll
        for (int i = 0; i < 16; i++) q += IS[i];
        s_is = q;
    }
    __syncthreads();
    if (tid < 64) {
        int uid = user_ids[b];
        v[tid] = user_table[uid * 64 + tid] + __fdividef(av, s_is) + sv;
    }
    __syncthreads();

    // ---- t-phase: 7 rounds (t = qw + 16*j), chunks {4,3} ----
    const float4 v0 = *(const float4*)&v[d8];
    const float4 v1 = *(const float4*)&v[d8 + 4];
    const int* tids = target_item_ids + b * T_;

    #pragma unroll
    for (int c = 0; c < 2; c++) {
        const int j0 = c ? 4 : 0, nj = c ? 3 : 4;
        int wid_[4]; float b2v[4]; float4 w0[4], w1[4];
        #pragma unroll
        for (int j = 0; j < 4; j++) {
            if (j < nj) {
                int t = qw + ((j0 + j) << 4);
                if (t >= T_) t = T_ - 1;
                wid_[j] = tids[t];
            }
        }
        #pragma unroll
        for (int j = 0; j < 4; j++) {
            if (j < nj) {
                w0[j] = *(const float4*)&W2_table[wid_[j] * 64 + d8];
                w1[j] = *(const float4*)&W2_table[wid_[j] * 64 + d8 + 4];
            }
        }
        #pragma unroll
        for (int j = 0; j < 4; j++)
            if (j < nj) b2v[j] = __ldg(&b2_table[wid_[j]]);
        #pragma unroll
        for (int j = 0; j < 4; j++) {
            if (j < nj) {
                float pp = w0[j].x*v0.x + w0[j].y*v0.y + w0[j].z*v0.z + w0[j].w*v0.w
                         + w1[j].x*v1.x + w1[j].y*v1.y + w1[j].z*v1.z + w1[j].w*v1.w;
                pp += __shfl_xor_sync(0xffffffffu, pp, 4);
                pp += __shfl_xor_sync(0xffffffffu, pp, 2);
                pp += __shfl_xor_sync(0xffffffffu, pp, 1);
                int t = qw + ((j0 + j) << 4);
                if (ql == 0 && t < T_) outS[t] = pp + b2v[j];
            }
        }
    }
    __syncthreads();
    if (tid < T_) out[b * T_ + tid] = outS[tid];
}

extern "C" void kernel_launch(void* const* d_in, const int* in_sizes, int n_in,
                              void* d_out, int out_size) {
    const int B = in_sizes[0] > B_MAX ? B_MAX : in_sizes[0];
    int R = in_sizes[4] / D_;
    if (R > I_MAX) R = I_MAX;
    const int nP = (R + 63) / 64;
    const int nU = (B + 15) / 16;

    k_pre<<<nP + nU, 128>>>(
        (const float*)d_in[4], (const float*)d_in[7],
        (const int*)d_in[0], (const float*)d_in[3], (const float*)d_in[9],
        (const float*)d_in[8], (const float*)d_in[10], (const float*)d_in[12],
        R, B, nP);

    k_main<<<B, 128>>>(
        (const int*)d_in[0], (const int*)d_in[1], (const int*)d_in[2],
        (const float*)d_in[3], (const float*)d_in[4], (const float*)d_in[5],
        (const float*)d_in[6], (const float*)d_in[11], (float*)d_out);
}